// round 10
// baseline (speedup 1.0000x reference)
#include <cuda_runtime.h>
#include <cstdint>

// ---------------------------------------------------------------------------
// QuanvolutionSamplerHybrid — closed-form circuit, f32x2 patch-pair matvec.
// Geometry experiment: 10 warps x 320 thr, 2 blocks/SM (20 warps, 102 regs)
// with manual software pipelining: feature tree of pair i+1 computed while
// matvec of pair i drains its LDS stream. Flat patch schedule:
// warps 0-7: pairs 10w..10w+9; warp 8: 80..88; warp 9: 89..97.
// ---------------------------------------------------------------------------

#define IMGS_PER_BLOCK 32
#define WARPS 10
#define THREADS (WARPS * 32)
#define PIX_STRIDE_B 1576              // bytes per image (784*2 + 8 pad)
#define PIX_BYTES (IMGS_PER_BLOCK * PIX_STRIDE_B)       // 50,432
#define WSLICE_B 1600                  // one patch-pair weight slice
#define WBUF_BYTES (WARPS * 2 * WSLICE_B)               // 32,000
#define SMEM_BYTES (PIX_BYTES + WBUF_BYTES)             // 82,432 -> 2 blocks/SM

typedef unsigned long long ull;

// weights packed [pair(98)][k(20)][class(10)][h(2: patchA/patchB)]
__device__ __align__(16) float g_wpack2[98 * 400];

__global__ void prep_kernel(const float* __restrict__ fc_w) {
    int idx = blockIdx.x * 256 + threadIdx.x;
    if (idx >= 39200) return;
    int p = idx / 400;
    int rem = idx - p * 400;
    int k = rem / 20;
    int rem2 = rem - k * 20;
    int c = rem2 >> 1;
    int h = rem2 & 1;
    int j = 2 * p + h;                 // patch index 0..195
    float v;
    if (k < 16) v = fc_w[c * 3920 + j * 16 + k];
    else        v = fc_w[c * 3920 + 3136 + j * 4 + (k - 16)];
    g_wpack2[idx] = v;
}

// ---- f32x2 helpers ----
__device__ __forceinline__ ull pk2(float lo, float hi) {
    ull r; asm("mov.b64 %0,{%1,%2};" : "=l"(r) : "f"(lo), "f"(hi)); return r;
}
__device__ __forceinline__ void upk2(ull v, float& lo, float& hi) {
    asm("mov.b64 {%0,%1},%2;" : "=f"(lo), "=f"(hi) : "l"(v));
}
__device__ __forceinline__ ull add2(ull a, ull b) {
    ull d; asm("add.rn.f32x2 %0,%1,%2;" : "=l"(d) : "l"(a), "l"(b)); return d;
}
__device__ __forceinline__ ull mul2(ull a, ull b) {
    ull d; asm("mul.rn.f32x2 %0,%1,%2;" : "=l"(d) : "l"(a), "l"(b)); return d;
}
__device__ __forceinline__ ull fma2(ull a, ull b, ull c) {
    ull d; asm("fma.rn.f32x2 %0,%1,%2,%3;" : "=l"(d) : "l"(a), "l"(b), "l"(c)); return d;
}

__device__ __forceinline__ uint32_t smem_u32(const void* p) {
    uint32_t a;
    asm("{ .reg .u64 t; cvta.to.shared.u64 t, %1; cvt.u32.u64 %0, t; }"
        : "=r"(a) : "l"(p));
    return a;
}
__device__ __forceinline__ void cpasync16(uint32_t dst, const void* src) {
    asm volatile("cp.async.cg.shared.global [%0], [%1], 16;"
                 :: "r"(dst), "l"(src) : "memory");
}
#define CP_COMMIT() asm volatile("cp.async.commit_group;" ::: "memory")
#define CP_WAIT(n)  asm volatile("cp.async.wait_group %0;" :: "n"(n) : "memory")
#define WARP_SYNC() asm volatile("bar.warp.sync 0xffffffff;" ::: "memory")

// per-warp: prefetch one 1600B pair slice (100 x 16B), one cp.async group
__device__ __forceinline__ void prefetch_slice(uint32_t dst, const char* src, int lane) {
    #pragma unroll
    for (int j = 0; j < 4; j++) {
        int e = lane + j * 32;
        if (e < 100) cpasync16(dst + e * 16, src + e * 16);
    }
    CP_COMMIT();
}

struct Feat {
    ull Q[4];
    ull M[4];
    ull s0q, o0, p3q, o3;
};

__device__ __forceinline__ Feat feat_for_pair(
    const char* pixbase, int p,
    ull SCL, ull ONE, ull N1, ull H2, ull NH2,
    ull K_S2, ull K_S1, ull K_C2, ull K_C1, float K9)
{
    // pair p = patches 2p, 2p+1; image row = p/7 pair-rows, col quad = p%7
    int q7 = p / 7;
    int r7 = p - q7 * 7;
    int offA = q7 * 112 + r7 * 8;
    ull a8 = *reinterpret_cast<const ull*>(pixbase + offA);
    ull b8 = *reinterpret_cast<const ull*>(pixbase + offA + 56);

    uint32_t alo = (uint32_t)a8, ahi = (uint32_t)(a8 >> 32);
    uint32_t blo = (uint32_t)b8, bhi = (uint32_t)(b8 >> 32);
    float p0A = (float)(alo & 0xFFFFu), p1A = (float)(alo >> 16);
    float p0B = (float)(ahi & 0xFFFFu), p1B = (float)(ahi >> 16);
    float p2A = (float)(blo & 0xFFFFu), p3A = (float)(blo >> 16);
    float p2B = (float)(bhi & 0xFFFFu), p3B = (float)(bhi >> 16);

    ull P0 = mul2(pk2(p0A, p0B), SCL);
    ull P1 = mul2(pk2(p1A, p1B), SCL);
    ull P2 = mul2(pk2(p2A, p2B), SCL);
    ull P3 = mul2(pk2(p3A, p3B), SCL);

    ull T0 = mul2(P0, P0), T1 = mul2(P1, P1);
    ull T2 = mul2(P2, P2), T3 = mul2(P3, P3);
    ull S0 = mul2(P0, fma2(T0, fma2(T0, K_S2, K_S1), H2));
    ull C0 = fma2(T0, fma2(T0, K_C2, K_C1), ONE);
    ull S1 = mul2(P1, fma2(T1, fma2(T1, K_S2, K_S1), H2));
    ull C1 = fma2(T1, fma2(T1, K_C2, K_C1), ONE);
    ull S2 = mul2(P2, fma2(T2, fma2(T2, K_S2, K_S1), H2));
    ull S3 = mul2(P3, fma2(T3, fma2(T3, K_S2, K_S1), H2));

    float s9a, c9a, s9b, c9b;
    __sincosf(K9 * p0A, &s9a, &c9a);
    __sincosf(K9 * p0B, &s9b, &c9b);
    ull C9 = pk2(c9a, c9b);
    ull S9 = pk2(s9a, s9b);

    ull CH = mul2(C1, H2);
    ull qh = fma2(S1, H2, CH);
    ull rh = fma2(S1, NH2, CH);
    ull tC = mul2(qh, C9), tS = mul2(qh, S9);
    ull rc = mul2(rh, C0), rs = mul2(rh, S0);
    ull x0 = add2(tC, rc), x1 = fma2(rc, N1, tC);
    ull y0 = add2(tS, rs), y1 = fma2(rs, N1, tS);

    Feat F;
    F.Q[0] = mul2(x0, x0); F.Q[1] = mul2(x1, x1);
    F.Q[2] = mul2(y0, y0); F.Q[3] = mul2(y1, y1);
    ull p2q = mul2(S2, S2);
    F.p3q = mul2(S3, S3);
    ull o2 = fma2(p2q, N1, ONE);
    F.o3 = fma2(F.p3q, N1, ONE);
    F.M[0] = mul2(o2, F.o3);  F.M[1] = mul2(o2, F.p3q);
    F.M[2] = mul2(p2q, F.o3); F.M[3] = mul2(p2q, F.p3q);
    F.s0q = mul2(S0, S0);
    F.o0 = fma2(F.s0q, N1, ONE);
    return F;
}

__device__ __forceinline__ ull feat_k(const Feat& F, int k) {
    if (k < 16)  return mul2(F.Q[k >> 2], F.M[k & 3]);
    if (k == 16) return mul2(F.o0, F.o3);
    if (k == 17) return mul2(F.o0, F.p3q);
    if (k == 18) return mul2(F.s0q, F.o3);
    return mul2(F.s0q, F.p3q);
}

__global__ __launch_bounds__(THREADS, 2)
void quanv_kernel(const float* __restrict__ x,
                  const float* __restrict__ fc_b,
                  float* __restrict__ out) {
    extern __shared__ char smem[];
    char* pix = smem;
    char* wbuf = smem + PIX_BYTES;
    const int tid = threadIdx.x;
    const int w = tid >> 5;
    const int lane = tid & 31;

    const int np = (w < 8) ? 10 : 9;
    const int pstart = (w < 8) ? 10 * w : (80 + 9 * (w - 8));
    const uint32_t mybuf = smem_u32(wbuf) + w * (2 * WSLICE_B);
    const char* wsrc = (const char*)g_wpack2 + pstart * WSLICE_B;

    // ---- Prologue: prefetch pair slices 0, 1 ----
    prefetch_slice(mybuf,            wsrc,            lane);
    prefetch_slice(mybuf + WSLICE_B, wsrc + WSLICE_B, lane);

    // ---- Stage 32 images as u16 fixed-point, coalesced ----
    const float4* xb =
        reinterpret_cast<const float4*>(x + (size_t)blockIdx.x * (IMGS_PER_BLOCK * 784));
    #pragma unroll 1
    for (int i = tid; i < IMGS_PER_BLOCK * 196; i += THREADS) {
        float4 v = xb[i];
        int img = i / 196;
        int q4 = i - img * 196;
        uint32_t u0 = __float2uint_rn(v.x * 65535.0f);
        uint32_t u1 = __float2uint_rn(v.y * 65535.0f);
        uint32_t u2 = __float2uint_rn(v.z * 65535.0f);
        uint32_t u3 = __float2uint_rn(v.w * 65535.0f);
        ull packed = (ull)(u0 | (u1 << 16)) | ((ull)(u2 | (u3 << 16)) << 32);
        *reinterpret_cast<ull*>(pix + img * PIX_STRIDE_B + q4 * 8) = packed;
    }
    __syncthreads();

    const float INV = 1.0f / 65535.0f;
    const float K9 = 4.5f / 65535.0f;
    const ull SCL  = pk2(INV, INV);
    const ull ONE  = pk2(1.0f, 1.0f);
    const ull N1   = pk2(-1.0f, -1.0f);
    const ull H2   = pk2(0.5f, 0.5f);
    const ull NH2  = pk2(-0.5f, -0.5f);
    const ull K_S2 = pk2(2.6041668e-4f, 2.6041668e-4f);
    const ull K_S1 = pk2(-2.0833334e-2f, -2.0833334e-2f);
    const ull K_C2 = pk2(2.6041667e-3f, 2.6041667e-3f);
    const ull K_C1 = pk2(-0.125f, -0.125f);

    ull acc2[10];
    #pragma unroll
    for (int c = 0; c < 10; c++) acc2[c] = 0ULL;

    const char* pixbase = pix + lane * PIX_STRIDE_B;

    // ---- Software-pipelined main loop ----
    Feat Fcur = feat_for_pair(pixbase, pstart, SCL, ONE, N1, H2, NH2,
                              K_S2, K_S1, K_C2, K_C1, K9);

    #pragma unroll 2
    for (int i = 0; i < np; i++) {
        if (i == np - 1) { CP_WAIT(0); } else { CP_WAIT(1); }
        WARP_SYNC();

        // overlap: feature tree of pair i+1 (no smem-weight dependency)
        Feat Fnext;
        bool more = (i + 1 < np);
        if (more)
            Fnext = feat_for_pair(pixbase, pstart + i + 1, SCL, ONE, N1, H2, NH2,
                                  K_S2, K_S1, K_C2, K_C1, K9);

        // matvec for pair i from smem slice (i&1)
        const ulonglong2* wp = reinterpret_cast<const ulonglong2*>(
            wbuf + w * (2 * WSLICE_B) + (i & 1) * WSLICE_B);
        #pragma unroll
        for (int k = 0; k < 20; k++) {
            ull Fk = feat_k(Fcur, k);
            const ulonglong2* wk = wp + k * 5;
            #pragma unroll
            for (int q = 0; q < 5; q++) {
                ulonglong2 wv = wk[q];
                acc2[2 * q]     = fma2(Fk, wv.x, acc2[2 * q]);
                acc2[2 * q + 1] = fma2(Fk, wv.y, acc2[2 * q + 1]);
            }
        }

        if (i + 2 < np) {
            WARP_SYNC();
            prefetch_slice(mybuf + (i & 1) * WSLICE_B,
                           wsrc + (i + 2) * WSLICE_B, lane);
        }
        if (more) Fcur = Fnext;
    }

    // collapse packed halves (patchA + patchB)
    float acc[10];
    #pragma unroll
    for (int c = 0; c < 10; c++) {
        float lo, hi;
        upk2(acc2[c], lo, hi);
        acc[c] = lo + hi;
    }

    // ---- Cross-warp reduction (overlay pixel smem; all warps done) ----
    __syncthreads();
    float* part = reinterpret_cast<float*>(pix);      // [10][32][10]
    #pragma unroll
    for (int c = 0; c < 10; c++)
        part[w * 320 + lane * 10 + c] = acc[c];
    __syncthreads();

    float* L = part + WARPS * 320;                    // [320] logits
    {
        float s = 0.0f;
        #pragma unroll
        for (int ww = 0; ww < WARPS; ww++) s += part[ww * 320 + tid];
        s += fc_b[tid % 10];
        L[tid] = s;
    }
    __syncthreads();

    float* lse = L + 320;                             // [32]
    if (tid < 32) {
        const float* Lr = L + tid * 10;
        float mx = Lr[0];
        #pragma unroll
        for (int c = 1; c < 10; c++) mx = fmaxf(mx, Lr[c]);
        float se = 0.0f;
        #pragma unroll
        for (int c = 0; c < 10; c++) se += __expf(Lr[c] - mx);
        lse[tid] = mx + __logf(se);
    }
    __syncthreads();

    out[blockIdx.x * 320 + tid] = L[tid] - lse[tid / 10];
}

extern "C" void kernel_launch(void* const* d_in, const int* in_sizes, int n_in,
                              void* d_out, int out_size) {
    const float* x    = (const float*)d_in[0];   // (8192,1,28,28)
    const float* fc_w = (const float*)d_in[1];   // (10,3920)
    const float* fc_b = (const float*)d_in[2];   // (10,)
    float* out = (float*)d_out;                  // (8192,10)
    (void)in_sizes; (void)n_in; (void)out_size;

    cudaFuncSetAttribute(quanv_kernel,
                         cudaFuncAttributeMaxDynamicSharedMemorySize, SMEM_BYTES);

    prep_kernel<<<(39200 + 255) / 256, 256>>>(fc_w);
    quanv_kernel<<<8192 / IMGS_PER_BLOCK, THREADS, SMEM_BYTES>>>(x, fc_b, out);
}

// round 12
// speedup vs baseline: 1.4494x; 1.4494x over previous
#include <cuda_runtime.h>
#include <cuda_bf16.h>
#include <cstdint>

// Quanvolution: producers (7 warps) emit bf16 features into smem A[32x296];
// warps 0-3 run portable mma.sync m16n8k16 (bf16->f32) accumulating logits
// over 14 steps. 2 blocks/SM. No tcgen05 (harness PTX target lacks 'a').
typedef unsigned long long ull;

#define WARPS 7
#define THREADS 224
#define STEPS 14
#define AST 592                      // A/B row stride bytes (148 words: conflict-free frags)
#define A_OFF 0
#define A_BYTES (32 * AST)           // 18944
#define BSTEP_B (16 * AST)           // 9472
#define B0_OFF 18944
#define B1_OFF 28416
#define PIX_OFF 37888
#define PIX_STRIDE_B 1576
#define PIX_BYTES (32 * PIX_STRIDE_B)  // 50432
#define SMEM_BYTES (PIX_OFF + PIX_BYTES)  // 88320 -> 2 blocks/SM

// Bt[step][class(16)][k(296)] bf16 (col-major B for row.col mma)
__device__ __align__(16) unsigned short g_wq[STEPS * 16 * 296];

__global__ void prep_kernel(const float* __restrict__ fc_w) {
    int idx = blockIdx.x * 256 + threadIdx.x;
    if (idx >= STEPS * 16 * 296) return;
    int s = idx / (16 * 296);
    int r2 = idx - s * (16 * 296);
    int r = r2 / 296;                  // class 0..15
    int c = r2 - r * 296;              // k col 0..295
    float v = 0.0f;
    if (r < 10 && c < 280) {
        int tcol = c / 40, rem = c - tcol * 40;
        int k = rem >> 1, h = rem & 1;
        int j = s * 14 + 2 * tcol + h; // patch 0..195
        v = (k < 16) ? fc_w[r * 3920 + j * 16 + k]
                     : fc_w[r * 3920 + 3136 + j * 4 + (k - 16)];
    }
    __nv_bfloat16 bv = __float2bfloat16(v);
    g_wq[idx] = *reinterpret_cast<unsigned short*>(&bv);
}

// f32x2 helpers
__device__ __forceinline__ ull pk2(float lo, float hi) {
    ull r; asm("mov.b64 %0,{%1,%2};" : "=l"(r) : "f"(lo), "f"(hi)); return r;
}
__device__ __forceinline__ void upk2(ull v, float& lo, float& hi) {
    asm("mov.b64 {%0,%1},%2;" : "=f"(lo), "=f"(hi) : "l"(v));
}
__device__ __forceinline__ ull add2(ull a, ull b) {
    ull d; asm("add.rn.f32x2 %0,%1,%2;" : "=l"(d) : "l"(a), "l"(b)); return d;
}
__device__ __forceinline__ ull mul2(ull a, ull b) {
    ull d; asm("mul.rn.f32x2 %0,%1,%2;" : "=l"(d) : "l"(a), "l"(b)); return d;
}
__device__ __forceinline__ ull fma2(ull a, ull b, ull c) {
    ull d; asm("fma.rn.f32x2 %0,%1,%2,%3;" : "=l"(d) : "l"(a), "l"(b), "l"(c)); return d;
}
// pack f32x2 (lo,hi) -> bf16x2 word, lo in low half
__device__ __forceinline__ uint32_t cvt2(ull v) {
    float lo, hi; upk2(v, lo, hi);
    uint32_t r;
    asm("cvt.rn.satfinite.bf16x2.f32 %0, %1, %2;" : "=r"(r) : "f"(hi), "f"(lo));
    return r;
}
__device__ __forceinline__ uint32_t smem_u32(const void* p) {
    uint32_t a;
    asm("{ .reg .u64 t; cvta.to.shared.u64 t, %1; cvt.u32.u64 %0, t; }"
        : "=r"(a) : "l"(p));
    return a;
}
__device__ __forceinline__ void cpasync16(uint32_t dst, const void* src) {
    asm volatile("cp.async.cg.shared.global [%0], [%1], 16;"
                 :: "r"(dst), "l"(src) : "memory");
}
#define CP_COMMIT() asm volatile("cp.async.commit_group;" ::: "memory")
#define CP_WAIT(n)  asm volatile("cp.async.wait_group %0;" :: "n"(n) : "memory")

__device__ __forceinline__ void mma16816(float& d0, float& d1, float& d2, float& d3,
                                         uint32_t a0, uint32_t a1, uint32_t a2, uint32_t a3,
                                         uint32_t b0, uint32_t b1) {
    asm volatile(
        "mma.sync.aligned.m16n8k16.row.col.f32.bf16.bf16.f32 "
        "{%0,%1,%2,%3}, {%4,%5,%6,%7}, {%8,%9}, {%0,%1,%2,%3};"
        : "+f"(d0), "+f"(d1), "+f"(d2), "+f"(d3)
        : "r"(a0), "r"(a1), "r"(a2), "r"(a3), "r"(b0), "r"(b1));
}

__global__ __launch_bounds__(THREADS, 2)
void quanv_kernel(const float* __restrict__ x,
                  const float* __restrict__ fc_b,
                  float* __restrict__ out) {
    extern __shared__ char smem[];
    const uint32_t sb = smem_u32(smem);
    const int tid = threadIdx.x;
    const int w = tid >> 5, lane = tid & 31;

    // prefetch B step 0
    for (int j = tid; j < BSTEP_B / 16; j += THREADS)
        cpasync16(sb + B0_OFF + j * 16, (const char*)g_wq + j * 16);
    CP_COMMIT();

    // zero A (covers k-pad cols 280..295)
    const uint4 z4 = {0u, 0u, 0u, 0u};
    for (int j = tid; j < A_BYTES / 16; j += THREADS)
        *reinterpret_cast<uint4*>(smem + A_OFF + j * 16) = z4;

    // stage 32 images as u16 fixed-point
    const float4* xb =
        reinterpret_cast<const float4*>(x + (size_t)blockIdx.x * (32 * 784));
    for (int i = tid; i < 32 * 196; i += THREADS) {
        float4 v = xb[i];
        int img = i / 196, q4 = i - img * 196;
        uint32_t u0 = __float2uint_rn(v.x * 65535.0f);
        uint32_t u1 = __float2uint_rn(v.y * 65535.0f);
        uint32_t u2 = __float2uint_rn(v.z * 65535.0f);
        uint32_t u3 = __float2uint_rn(v.w * 65535.0f);
        ull pk = (ull)(u0 | (u1 << 16)) | ((ull)(u2 | (u3 << 16)) << 32);
        *reinterpret_cast<ull*>(smem + PIX_OFF + img * PIX_STRIDE_B + q4 * 8) = pk;
    }
    __syncthreads();

    const ull ONE  = pk2(1.0f, 1.0f);
    const ull N1   = pk2(-1.0f, -1.0f);
    const ull H2   = pk2(0.5f, 0.5f);
    const ull NH2  = pk2(-0.5f, -0.5f);
    const ull K_S2 = pk2(2.6041668e-4f, 2.6041668e-4f);
    const ull K_S1 = pk2(-2.0833334e-2f, -2.0833334e-2f);
    const ull K_C2 = pk2(2.6041667e-3f, 2.6041667e-3f);
    const ull K_C1 = pk2(-0.125f, -0.125f);
    const float INV = 1.0f / 65535.0f;
    const float K9 = 4.5f / 65535.0f;
    const ull SCL = pk2(INV, INV);

    // producer: lane = image row, w = pair col; A row base
    char* arow = smem + A_OFF + lane * AST + w * 80;
    const char* pixme = smem + PIX_OFF + lane * PIX_STRIDE_B + 8 * w;

    // consumer (warps 0-3): mt = w>>1 (imgs 16mt..), nt = w&1 (classes 8nt..)
    float d0 = 0.f, d1 = 0.f, d2 = 0.f, d3 = 0.f;
    const int mt = w >> 1, nt = w & 1;
    const char* aF = smem + A_OFF + (mt * 16 + (lane >> 2)) * AST + (lane & 3) * 4;
    const int bBaseOff = ((nt * 8 + (lane >> 2)) * AST + (lane & 3) * 4);

    #pragma unroll 1
    for (int s = 0; s < STEPS; s++) {
        if (s + 1 < STEPS) {
            const char* src = (const char*)g_wq + (s + 1) * BSTEP_B;
            uint32_t dst = sb + (((s + 1) & 1) ? B1_OFF : B0_OFF);
            for (int j = tid; j < BSTEP_B / 16; j += THREADS)
                cpasync16(dst + j * 16, src + j * 16);
            CP_COMMIT();
        }

        {   // features for (patch row s, pair col w), both patches packed f32x2
            const char* pA = pixme + s * 112;
            ull a8 = *reinterpret_cast<const ull*>(pA);
            ull b8 = *reinterpret_cast<const ull*>(pA + 56);
            uint32_t alo = (uint32_t)a8, ahi = (uint32_t)(a8 >> 32);
            uint32_t blo = (uint32_t)b8, bhi = (uint32_t)(b8 >> 32);
            float p0A = (float)(alo & 0xFFFFu), p1A = (float)(alo >> 16);
            float p0B = (float)(ahi & 0xFFFFu), p1B = (float)(ahi >> 16);
            float p2A = (float)(blo & 0xFFFFu), p3A = (float)(blo >> 16);
            float p2B = (float)(bhi & 0xFFFFu), p3B = (float)(bhi >> 16);
            ull P0 = mul2(pk2(p0A, p0B), SCL), P1 = mul2(pk2(p1A, p1B), SCL);
            ull P2 = mul2(pk2(p2A, p2B), SCL), P3 = mul2(pk2(p3A, p3B), SCL);
            ull T0 = mul2(P0, P0), T1 = mul2(P1, P1);
            ull T2 = mul2(P2, P2), T3 = mul2(P3, P3);
            ull S0 = mul2(P0, fma2(T0, fma2(T0, K_S2, K_S1), H2));
            ull C0 = fma2(T0, fma2(T0, K_C2, K_C1), ONE);
            ull S1 = mul2(P1, fma2(T1, fma2(T1, K_S2, K_S1), H2));
            ull C1 = fma2(T1, fma2(T1, K_C2, K_C1), ONE);
            ull S2 = mul2(P2, fma2(T2, fma2(T2, K_S2, K_S1), H2));
            ull S3 = mul2(P3, fma2(T3, fma2(T3, K_S2, K_S1), H2));
            float s9a, c9a, s9b, c9b;
            __sincosf(K9 * p0A, &s9a, &c9a);
            __sincosf(K9 * p0B, &s9b, &c9b);
            ull C9 = pk2(c9a, c9b), S9 = pk2(s9a, s9b);
            ull CH = mul2(C1, H2);
            ull qh = fma2(S1, H2, CH), rh = fma2(S1, NH2, CH);
            ull tC = mul2(qh, C9), tS = mul2(qh, S9);
            ull rc = mul2(rh, C0), rs = mul2(rh, S0);
            ull x0 = add2(tC, rc), x1 = fma2(rc, N1, tC);
            ull y0 = add2(tS, rs), y1 = fma2(rs, N1, tS);
            ull Q[4] = {mul2(x0, x0), mul2(x1, x1), mul2(y0, y0), mul2(y1, y1)};
            ull p2q = mul2(S2, S2), p3q = mul2(S3, S3);
            ull o2 = fma2(p2q, N1, ONE), o3 = fma2(p3q, N1, ONE);
            ull M[4] = {mul2(o2, o3), mul2(o2, p3q), mul2(p2q, o3), mul2(p2q, p3q)};
            ull s0q = mul2(S0, S0), o0 = fma2(s0q, N1, ONE);
            uint32_t fw[20];
            #pragma unroll
            for (int k = 0; k < 16; k++) fw[k] = cvt2(mul2(Q[k >> 2], M[k & 3]));
            fw[16] = cvt2(mul2(o0, o3));  fw[17] = cvt2(mul2(o0, p3q));
            fw[18] = cvt2(mul2(s0q, o3)); fw[19] = cvt2(mul2(s0q, p3q));
            #pragma unroll
            for (int m = 0; m < 10; m++) {
                ull pkd = (ull)fw[2 * m] | ((ull)fw[2 * m + 1] << 32);
                *reinterpret_cast<ull*>(arow + m * 8) = pkd;
            }
        }

        if (s + 1 < STEPS) { CP_WAIT(1); } else { CP_WAIT(0); }
        __syncthreads();              // A written, B[s] resident

        if (w < 4) {
            const char* bF = smem + ((s & 1) ? B1_OFF : B0_OFF) + bBaseOff;
            #pragma unroll
            for (int j = 0; j < 18; j++) {
                uint32_t a0 = *reinterpret_cast<const uint32_t*>(aF + 32 * j);
                uint32_t a1 = *reinterpret_cast<const uint32_t*>(aF + 32 * j + 8 * AST);
                uint32_t a2 = *reinterpret_cast<const uint32_t*>(aF + 32 * j + 16);
                uint32_t a3 = *reinterpret_cast<const uint32_t*>(aF + 32 * j + 8 * AST + 16);
                uint32_t b0 = *reinterpret_cast<const uint32_t*>(bF + 32 * j);
                uint32_t b1 = *reinterpret_cast<const uint32_t*>(bF + 32 * j + 16);
                mma16816(d0, d1, d2, d3, a0, a1, a2, a3, b0, b1);
            }
        }
        __syncthreads();              // consumers done before A overwritten
    }

    // epilogue: frags -> logits smem (overlay pix), logsoftmax
    float* Lp = reinterpret_cast<float*>(smem + PIX_OFF);   // [32][16]
    if (w < 4) {
        int row = mt * 16 + (lane >> 2);
        int col = nt * 8 + (lane & 3) * 2;
        Lp[row * 16 + col] = d0;
        Lp[row * 16 + col + 1] = d1;
        Lp[(row + 8) * 16 + col] = d2;
        Lp[(row + 8) * 16 + col + 1] = d3;
    }
    __syncthreads();

    if (tid < 32) {
        const float* Lr = Lp + tid * 16;
        float L[10];
        #pragma unroll
        for (int c = 0; c < 10; c++) L[c] = Lr[c] + __ldg(fc_b + c);
        float mx = L[0];
        #pragma unroll
        for (int c = 1; c < 10; c++) mx = fmaxf(mx, L[c]);
        float se = 0.0f;
        #pragma unroll
        for (int c = 0; c < 10; c++) se += __expf(L[c] - mx);
        float lse = mx + __logf(se);
        float* op = out + blockIdx.x * 320 + tid * 10;
        #pragma unroll
        for (int c = 0; c < 10; c++) op[c] = L[c] - lse;
    }
}

extern "C" void kernel_launch(void* const* d_in, const int* in_sizes, int n_in,
                              void* d_out, int out_size) {
    const float* x    = (const float*)d_in[0];
    const float* fc_w = (const float*)d_in[1];
    const float* fc_b = (const float*)d_in[2];
    float* out = (float*)d_out;
    (void)in_sizes; (void)n_in; (void)out_size;

    cudaFuncSetAttribute(quanv_kernel,
                         cudaFuncAttributeMaxDynamicSharedMemorySize, SMEM_BYTES);

    prep_kernel<<<(STEPS * 16 * 296 + 255) / 256, 256>>>(fc_w);
    quanv_kernel<<<256, THREADS, SMEM_BYTES>>>(x, fc_b, out);
}